// round 14
// baseline (speedup 1.0000x reference)
#include <cuda_runtime.h>
#include <cstdint>
#include <cstddef>

#define B_   8
#define T_   200
#define U_   50
#define V_   1024
#define UM1  (U_ - 1)

#define S_    312                 // smem column stride (floats); 2*(S_-1)%32=14 -> 2-way
#define NC    64                  // columns allocated per slab (ghosts up to 63)
#define SLABF (NC * S_)           // 19968 floats per slab
#define GSTR  208                 // gmem column stride (floats, 16B aligned)

#define LN2   0.6931471805599453f
#define NEGINF (-1e30f)

// __device__ globals zero-initialized. Columns u>ui are never written -> 0.
__device__ float g_bcol[B_ * 64 * GSTR];   // blank prob column (b,u): [t]
__device__ float g_ecol[B_ * 64 * GSTR];   // emit-into-u prob column (b,u): [t]
__device__ int   g_flag[B_ * 64];          // gather warp (b,u) done
__device__ float g_res [B_];
__device__ int   g_done;

__device__ __forceinline__ float lg2a(float x) {
    float r; asm("lg2.approx.f32 %0, %1;" : "=f"(r) : "f"(x)); return r;
}
__device__ __forceinline__ float rcpa(float x) {
    float r; asm("rcp.approx.f32 %0, %1;" : "=f"(r) : "f"(x)); return r;
}

// ---------------------------------------------------------------------------
// 108 blocks x 256 threads, single wave (<=148 SMs), 160KB smem -> 1 blk/SM.
//  blocks 8..107 : gather (warps 0-3, one (b,u) column each; 400 total).
//                  Coalesced column-major stores + release flag.
//  blocks 0..7   : DP for batch bid. 7 staging warps copy columns into smem
//                  as flags arrive (L2 hits); warp 0 runs the wavefront,
//                  gating each 8-diagonal group on the columns it touches.
// ---------------------------------------------------------------------------
__global__ __launch_bounds__(256) void k_fused(const float* __restrict__ h,
                                               const int*   __restrict__ targets,
                                               const int*   __restrict__ ilen,
                                               const int*   __restrict__ tlen,
                                               float*       __restrict__ out) {
    extern __shared__ float smem[];
    const int tid  = threadIdx.x;
    const int wid  = tid >> 5;
    const int lane = tid & 31;
    const int bid  = blockIdx.x;

    // ========================= GATHER role =========================
    if (bid >= B_) {
        if (wid >= 4) return;
        const int c = (bid - B_) * 4 + wid;          // 0..399
        const int b = c / U_;
        const int u = c - b * U_;
        const int ui = tlen[b] - 1;                  // [24,49]
        if (u > ui) return;                          // unreachable column

        const bool hasE = (u < ui);
        const int  tgt  = hasE ? targets[b * UM1 + u] : 1;
        const float* base = h + ((size_t)(b * T_) * U_ + u) * V_;

        float vb[7], ve[7];
        #pragma unroll
        for (int k = 0; k < 7; ++k) {
            const int t = lane + 32 * k;
            const bool val = (t < T_);
            const float* p = base + (size_t)t * (U_ * V_);
            vb[k] = val ? __ldg(p) : NEGINF;
            ve[k] = (val && hasE) ? __ldg(p + tgt) : NEGINF;
        }

        float M0 = vb[0], M1 = ve[0];
        #pragma unroll
        for (int k = 1; k < 7; ++k) { M0 = fmaxf(M0, vb[k]); M1 = fmaxf(M1, ve[k]); }
        #pragma unroll
        for (int o = 16; o > 0; o >>= 1) {
            M0 = fmaxf(M0, __shfl_xor_sync(0xffffffffu, M0, o));
            M1 = fmaxf(M1, __shfl_xor_sync(0xffffffffu, M1, o));
        }

        float eb[7], ee[7], S0 = 0.0f, S1 = 0.0f;
        #pragma unroll
        for (int k = 0; k < 7; ++k) {
            eb[k] = __expf(vb[k] - M0); S0 += eb[k];
            ee[k] = __expf(ve[k] - M1); S1 += ee[k];
        }
        #pragma unroll
        for (int o = 16; o > 0; o >>= 1) {
            S0 += __shfl_xor_sync(0xffffffffu, S0, o);
            S1 += __shfl_xor_sync(0xffffffffu, S1, o);
        }
        const float r0 = rcpa(S0);
        const float r1 = rcpa(S1);

        float* dstB = g_bcol + (size_t)(b * 64 + u) * GSTR;
        float* dstE = g_ecol + (size_t)(b * 64 + u + 1) * GSTR;
        #pragma unroll
        for (int k = 0; k < 7; ++k) {
            const int t = lane + 32 * k;
            if (t < T_) {
                dstB[t] = eb[k] * r0;                 // coalesced 128B lines
                if (hasE) dstE[t] = ee[k] * r1;
            }
        }
        __threadfence();                              // release
        __syncwarp();
        if (lane == 0) atomicExch(&g_flag[b * 64 + u], 1);
        return;
    }

    // ========================= DP role (blocks 0..7) =========================
    float* sB = smem;                    // [NC][S_] blank, col-major, 62 t-ghosts low
    float* sE = smem + SLABF;            // [NC][S_] emit-into-u
    int*   s_task = (int*)(smem + 2 * SLABF);   // 64 flags

    {   // zero both slabs + task flags
        float4* s4 = (float4*)smem;
        const float4 z4 = make_float4(0.f, 0.f, 0.f, 0.f);
        for (int i = tid; i < (2 * SLABF + 64) / 4; i += 256) s4[i] = z4;
    }
    __syncthreads();

    const int ti = ilen[bid] - 1;        // [99, 199]
    const int ui = tlen[bid] - 1;        // [24, 49]

    if (wid != 0) {
        // ---- staging warps 1..7: copy columns as they arrive ----
        for (int w = wid - 1; w <= ui; w += 7) {
            while (((volatile int*)g_flag)[bid * 64 + w] == 0) { }
            if (w > 0)
                while (((volatile int*)g_flag)[bid * 64 + w - 1] == 0) { }
            __threadfence();             // acquire

            const float4* srcB = (const float4*)(g_bcol + (size_t)(bid * 64 + w) * GSTR);
            float* dB = sB + w * S_ + 62;
            #pragma unroll 2
            for (int j = lane; j < 50; j += 32) {
                const float4 v = srcB[j];
                dB[4*j] = v.x; dB[4*j+1] = v.y; dB[4*j+2] = v.z; dB[4*j+3] = v.w;
            }
            if (w > 0) {
                const float4* srcE = (const float4*)(g_ecol + (size_t)(bid * 64 + w) * GSTR);
                float* dE = sE + w * S_ + 62;
                #pragma unroll 2
                for (int j = lane; j < 50; j += 32) {
                    const float4 v = srcE[j];
                    dE[4*j] = v.x; dE[4*j+1] = v.y; dE[4*j+2] = v.z; dE[4*j+3] = v.w;
                }
            }
            __threadfence_block();       // release within block
            __syncwarp();
            if (lane == 0) ((volatile int*)s_task)[w] = 1;
        }
        return;
    }

    // ---- DP warp (warp 0) ----
    const int dmax = ti + ui;

    // flat index of blank[t0-1][u0] at d: o = u0*S_ + 62 + (t0-1) = 622*lane + 61 + d
    int idx = 622 * lane + 62;           // at d = 1

    float p0 = (lane == 0) ? 1.0f : 0.0f;
    float p1 = 0.0f;
    int   L  = 0;                        // warp-uniform frame exponent
    int   staged = -1;

    #define DP_STEP(o)                                                        \
    {                                                                         \
        const float lp  = __shfl_up_sync(0xffffffffu, p1, 1);                 \
        const float cbA = sB[o];                                              \
        const float ceA = sE[(o) + 1];                                        \
        const float cbB = sB[(o) + 311];                                      \
        const float ceB = sE[(o) + 312];                                      \
        const float n0  = fmaf(p0, cbA, lp * ceA);                            \
        const float n1  = fmaf(p1, cbB, p0 * ceB);                            \
        p0 = n0; p1 = n1;                                                     \
    }

    const int ngroups = dmax >> 3;
    for (int g = 0; g < ngroups; ++g) {
        // gate: group g touches columns up to min(8(g+1), ui)
        const int target = min(8 * (g + 1), ui);
        if (staged < target) {
            while (staged < target) {
                ++staged;
                while (((volatile int*)s_task)[staged] == 0) { }
            }
            __threadfence_block();       // acquire staged data
        }

        #pragma unroll
        for (int k = 0; k < 8; ++k) DP_STEP(idx + k)
        idx += 8;

        // warp-uniform renorm from a reference active lane on diagonal dcur
        const int dcur = 8 * (g + 1);
        int lo = dcur - (T_ - 1);
        lo = (lo > 0) ? ((lo + 1) >> 1) : 0;
        const int hi  = min(ui >> 1, dcur >> 1);
        const int ref = (lo + hi) >> 1;

        float pr = __shfl_sync(0xffffffffu, p0, ref);
        pr = (pr > 0.0f) ? pr : 1.0f;
        const int e = (int)(__float_as_uint(pr) >> 23) - 127;
        L += e;
        const float fs = __uint_as_float((unsigned)(127 - e) << 23);  // 2^-e
        p0 *= fs; p1 *= fs;
    }

    const int tail = dmax & 7;
    for (int k = 0; k < tail; ++k) DP_STEP(idx + k)

    #undef DP_STEP

    // reset this batch's flags for the next graph replay (all consumed above)
    for (int i = lane; i < 64; i += 32) g_flag[bid * 64 + i] = 0;

    // publish; last finisher computes the mean and resets g_done
    if (lane == (ui >> 1)) {
        const float pf = (ui & 1) ? p1 : p0;
        const float bf = sB[ui * S_ + 62 + ti];
        g_res[bid] = -(lg2a(pf * bf) + (float)L) * LN2;
        __threadfence();
        const int old = atomicAdd(&g_done, 1);
        if (old == B_ - 1) {
            __threadfence();
            float s = 0.0f;
            #pragma unroll
            for (int i = 0; i < B_; ++i) s += g_res[i];
            out[0] = s * (1.0f / B_);
            g_done = 0;
            __threadfence();
        }
    }
}

// ---------------------------------------------------------------------------
extern "C" void kernel_launch(void* const* d_in, const int* in_sizes, int n_in,
                              void* d_out, int out_size) {
    const float* h       = (const float*)d_in[0];
    const int*   targets = (const int*)  d_in[1];
    const int*   il      = (const int*)  d_in[2];
    const int*   tl      = (const int*)  d_in[3];
    float*       out     = (float*)d_out;

    const int smem_bytes = (2 * SLABF + 64) * (int)sizeof(float);  // 160000
    cudaFuncSetAttribute(k_fused, cudaFuncAttributeMaxDynamicSharedMemorySize,
                         smem_bytes);

    k_fused<<<B_ + 100, 256, smem_bytes>>>(h, targets, il, tl, out);
}

// round 15
// speedup vs baseline: 1.0563x; 1.0563x over previous
#include <cuda_runtime.h>
#include <cstdint>
#include <cstddef>

#define B_   8
#define T_   200
#define U_   50
#define V_   1024
#define UM1  (U_ - 1)

#define ROWS 311            // 62 ghost rows below, 200 data, 49 ghost above
#define PADW 64             // row width (cols 50..63 always zero)
#define SLAB (ROWS * PADW)  // 19904 floats per (batch, slab)

#define LN2   0.6931471805599453f
#define NEGINF (-1e30f)

// __device__ globals zero-initialized; kernels only write data cells, so all
// margin rows/cols (and skipped u > ui columns) stay exactly 0.
// Coefficients are PRE-SCALED by 2^7 (exact) so DP values drift ~-0.6 bit/step
// instead of -8.3, allowing renorm every 32 steps.
__device__ float g_blank[B_ * SLAB];   // 128 * blank prob, row 63+t, col u
__device__ float g_emit [B_ * SLAB];   // 128 * emit prob,  row 62+t, col u+1
__device__ float g_res  [B_];
__device__ int   g_cnt  [B_];          // per-batch column arrivals (reset at end)
__device__ int   g_done;               // finished DP lanes        (reset at end)

__device__ __forceinline__ float lg2a(float x) {
    float r; asm("lg2.approx.f32 %0, %1;" : "=f"(r) : "f"(x)); return r;
}
__device__ __forceinline__ float rcpa(float x) {
    float r; asm("rcp.approx.f32 %0, %1;" : "=f"(r) : "f"(x)); return r;
}

// ---------------------------------------------------------------------------
// ONE fused kernel. 100 blocks x 256 threads, 159KB smem -> 1 block/SM,
// single wave, so inter-block spin-waits cannot deadlock.
//  * warps 0-3 of every block: gather/softmax for 4 (b,u) columns.
//  * blocks 0-7: DP for batch = blockIdx after gating on all 50 columns.
// ---------------------------------------------------------------------------
__global__ __launch_bounds__(256) void k_fused(const float* __restrict__ h,
                                               const int*   __restrict__ targets,
                                               const int*   __restrict__ ilen,
                                               const int*   __restrict__ tlen,
                                               float*       __restrict__ out) {
    extern __shared__ float smem[];
    const int tid  = threadIdx.x;
    const int wid  = tid >> 5;
    const int lane = tid & 31;
    const int bid  = blockIdx.x;

    // ================= LSE role (warps 0..3 of every block) =================
    if (wid < 4) {
        const int bu = bid * 4 + wid;                 // 0..399
        const int b  = bu / U_;
        const int u  = bu - b * U_;
        const int uiB = tlen[b] - 1;                  // [24,49]

        if (u <= uiB) {                               // reachable column
            const bool hasE = (u < uiB);
            const int  tgt  = hasE ? targets[b * UM1 + u] : 1;
            const float* base = h + ((size_t)(b * T_) * U_ + u) * V_;

            float vb[7], ve[7];
            #pragma unroll
            for (int k = 0; k < 7; ++k) {
                const int t = lane + 32 * k;
                const bool val = (t < T_);
                const float* p = base + (size_t)t * (U_ * V_);
                vb[k] = val ? __ldg(p) : NEGINF;
                ve[k] = (val && hasE) ? __ldg(p + tgt) : NEGINF;
            }

            float M0 = vb[0], M1 = ve[0];
            #pragma unroll
            for (int k = 1; k < 7; ++k) { M0 = fmaxf(M0, vb[k]); M1 = fmaxf(M1, ve[k]); }
            #pragma unroll
            for (int o = 16; o > 0; o >>= 1) {
                M0 = fmaxf(M0, __shfl_xor_sync(0xffffffffu, M0, o));
                M1 = fmaxf(M1, __shfl_xor_sync(0xffffffffu, M1, o));
            }

            float eb[7], ee[7], S0 = 0.0f, S1 = 0.0f;
            #pragma unroll
            for (int k = 0; k < 7; ++k) {
                eb[k] = __expf(vb[k] - M0); S0 += eb[k];
                ee[k] = __expf(ve[k] - M1); S1 += ee[k];
            }
            #pragma unroll
            for (int o = 16; o > 0; o >>= 1) {
                S0 += __shfl_xor_sync(0xffffffffu, S0, o);
                S1 += __shfl_xor_sync(0xffffffffu, S1, o);
            }
            const float r0 = rcpa(S0) * 128.0f;       // prescale by 2^7 (exact)
            const float r1 = rcpa(S1) * 128.0f;

            float* gb = g_blank + b * SLAB;
            float* ge = g_emit  + b * SLAB;
            #pragma unroll
            for (int k = 0; k < 7; ++k) {
                const int t = lane + 32 * k;
                if (t < T_) {
                    gb[(63 + t) * PADW + u] = eb[k] * r0;
                    if (hasE) ge[(62 + t) * PADW + (u + 1)] = ee[k] * r1;
                }
            }
        }
        __threadfence();                              // release
        __syncwarp();
        if (lane == 0) atomicAdd(&g_cnt[b], 1);
    }

    if (bid >= B_) return;          // non-DP blocks done

    // ================= DP role (blocks 0..7) =================
    float* sb = smem;               // [ROWS][PADW] blank slab
    float* se = smem + SLAB;        // [ROWS][PADW] emit slab

    const int ti = ilen[bid] - 1;   // [99, 199]
    const int ui = tlen[bid] - 1;   // [24, 49]
    const int dmax = ti + ui;

    {   // zero ghost rows BEFORE the gate (needs no data)
        float4* s4 = (float4*)smem;
        const float4 z4 = make_float4(0.f, 0.f, 0.f, 0.f);
        const int Q = SLAB / 4;
        for (int i = tid; i < 62 * 16; i += 256) { s4[i] = z4; s4[i + Q] = z4; }
        for (int i = tid; i < 48 * 16; i += 256) {
            s4[263 * 16 + i] = z4; s4[263 * 16 + Q + i] = z4;
        }
    }

    if (tid == 0) {                 // gate: all 50 columns of this batch
        while (((volatile int*)g_cnt)[bid] != U_) { }
        __threadfence();            // acquire
    }
    __syncthreads();

    {   // stage only rows 62 .. 62+dmax (wavefront never reads beyond)
        const int nrows = min(dmax + 1, 201);
        float4* s4 = (float4*)smem;
        const int Q = SLAB / 4;
        const float4* gb = (const float4*)(g_blank + bid * SLAB);
        const float4* ge = (const float4*)(g_emit  + bid * SLAB);
        #pragma unroll 4
        for (int i = tid; i < nrows * 16; i += 256) {
            s4[62 * 16 + i]     = gb[62 * 16 + i];
            s4[62 * 16 + Q + i] = ge[62 * 16 + i];
        }
    }
    __syncthreads();
    if (wid != 0) return;           // only warp 0 continues

    int idx = (63 - 2 * lane) * PADW + 2 * lane;   // row of cell (t0,u0) at d=1

    float p0 = (lane == 0) ? 1.0f : 0.0f;          // alpha'[0][0] = 1
    float p1 = 0.0f;
    int   L  = 0;                                  // warp-uniform frame exponent

    #define DP_STEP(o)                                                        \
    {                                                                         \
        const float lp  = __shfl_up_sync(0xffffffffu, p1, 1);                 \
        const float cbA = sb[o];                                              \
        const float ceA = se[o];                                              \
        const float cbB = sb[(o) - PADW + 1];                                 \
        const float ceB = se[(o) - PADW + 1];                                 \
        const float n0  = fmaf(p0, cbA, lp * ceA);                            \
        const float n1  = fmaf(p1, cbB, p0 * ceB);                            \
        p0 = n0; p1 = n1;                                                     \
    }

    const int ngroups = dmax >> 5;                 // renorm every 32 steps
    for (int g = 0; g < ngroups; ++g) {
        #pragma unroll
        for (int k = 0; k < 32; ++k) DP_STEP(idx + k * PADW)
        idx += 32 * PADW;

        // warp-uniform renorm from a reference active lane on diagonal dcur
        const int dcur = 32 * (g + 1);
        int lo = dcur - (T_ - 1);
        lo = (lo > 0) ? ((lo + 1) >> 1) : 0;
        const int hi  = min(ui >> 1, dcur >> 1);
        const int ref = (lo + hi) >> 1;

        float pr = __shfl_sync(0xffffffffu, p0, ref);
        pr = (pr > 0.0f) ? pr : 1.0f;
        const int e = (int)(__float_as_uint(pr) >> 23) - 127;
        L += e;
        const float fs = __uint_as_float((unsigned)(127 - e) << 23);  // 2^-e
        p0 *= fs; p1 *= fs;
    }

    const int tail = dmax & 31;
    for (int k = 0; k < tail; ++k) DP_STEP(idx + k * PADW)

    #undef DP_STEP

    // answer: alpha[ti][ui]*blank = pf*bf * 2^(L - 7*(dmax+1))
    if (lane == (ui >> 1)) {
        const float pf = (ui & 1) ? p1 : p0;
        const float bf = sb[(63 + ti) * PADW + ui];
        g_res[bid] = -(lg2a(pf * bf) + (float)(L - 7 * (dmax + 1))) * LN2;
        __threadfence();
        const int old = atomicAdd(&g_done, 1);
        if (old == B_ - 1) {
            __threadfence();                       // acquire all g_res
            float s = 0.0f;
            #pragma unroll
            for (int i = 0; i < B_; ++i) s += g_res[i];
            out[0] = s * (1.0f / B_);
            #pragma unroll
            for (int i = 0; i < B_; ++i) g_cnt[i] = 0;   // reset for replay
            g_done = 0;
            __threadfence();
        }
    }
}

// ---------------------------------------------------------------------------
extern "C" void kernel_launch(void* const* d_in, const int* in_sizes, int n_in,
                              void* d_out, int out_size) {
    const float* h       = (const float*)d_in[0];
    const int*   targets = (const int*)  d_in[1];
    const int*   il      = (const int*)  d_in[2];
    const int*   tl      = (const int*)  d_in[3];
    float*       out     = (float*)d_out;

    const int smem_bytes = 2 * SLAB * (int)sizeof(float);  // 159232
    cudaFuncSetAttribute(k_fused, cudaFuncAttributeMaxDynamicSharedMemorySize,
                         smem_bytes);

    k_fused<<<100, 256, smem_bytes>>>(h, targets, il, tl, out);
}

// round 16
// speedup vs baseline: 1.4564x; 1.3788x over previous
#include <cuda_runtime.h>
#include <cstdint>
#include <cstddef>

#define B_   8
#define T_   200
#define U_   50
#define V_   1024
#define UM1  (U_ - 1)

#define ROWS 311            // 62 ghost rows below, 200 data, 49 ghost above
#define PADW 64             // row width (cols 50..63 always zero)
#define SLAB (ROWS * PADW)  // 19904 floats per (batch, slab)

#define LN2   0.6931471805599453f
#define NEGINF (-1e30f)

// __device__ globals zero-initialized; kernels only write data cells, so all
// margin rows/cols (and skipped u > ui columns) stay exactly 0.
// Coefficients PRE-SCALED by 2^7 (exact): DP drift ~-1.3 bit/step instead of
// -8.3, so warp-uniform renorm is needed only every 32 steps.
__device__ float g_blank[B_ * SLAB];   // 128 * blank prob, row 63+t, col u
__device__ float g_emit [B_ * SLAB];   // 128 * emit prob,  row 62+t, col u+1
__device__ float g_res  [B_];
__device__ int   g_done;               // finished DP blocks (reset by finisher)

__device__ __forceinline__ float lg2a(float x) {
    float r; asm("lg2.approx.f32 %0, %1;" : "=f"(r) : "f"(x)); return r;
}
__device__ __forceinline__ float rcpa(float x) {
    float r; asm("rcp.approx.f32 %0, %1;" : "=f"(r) : "f"(x)); return r;
}

// ---------------------------------------------------------------------------
// Kernel A: warp per (b,u). Softmax over full T; warps for unreachable
// columns (u > tlen[b]-1) exit before issuing h loads. 100 x 128 shape
// (the best-measured gather configuration).
// ---------------------------------------------------------------------------
__global__ __launch_bounds__(128) void k_lse(const float* __restrict__ h,
                                             const int*   __restrict__ targets,
                                             const int*   __restrict__ tlen) {
    const int w    = threadIdx.x >> 5;
    const int lane = threadIdx.x & 31;
    const int bu   = blockIdx.x * 4 + w;          // 0..399
    const int b    = bu / U_;
    const int u    = bu - b * U_;

    const int ui = tlen[b] - 1;                   // [24, 49]
    if (u > ui) return;                           // unreachable column
    const bool hasE = (u < ui);
    const int  tgt  = hasE ? targets[b * UM1 + u] : 1;

    const float* base = h + ((size_t)(b * T_) * U_ + u) * V_;

    float vb[7], ve[7];
    #pragma unroll
    for (int k = 0; k < 7; ++k) {
        const int t = lane + 32 * k;
        const bool val = (t < T_);
        const float* p = base + (size_t)t * (U_ * V_);
        vb[k] = val ? __ldg(p) : NEGINF;
        ve[k] = (val && hasE) ? __ldg(p + tgt) : NEGINF;
    }

    float M0 = vb[0], M1 = ve[0];
    #pragma unroll
    for (int k = 1; k < 7; ++k) { M0 = fmaxf(M0, vb[k]); M1 = fmaxf(M1, ve[k]); }
    #pragma unroll
    for (int o = 16; o > 0; o >>= 1) {
        M0 = fmaxf(M0, __shfl_xor_sync(0xffffffffu, M0, o));
        M1 = fmaxf(M1, __shfl_xor_sync(0xffffffffu, M1, o));
    }

    float eb[7], ee[7], S0 = 0.0f, S1 = 0.0f;
    #pragma unroll
    for (int k = 0; k < 7; ++k) {
        eb[k] = __expf(vb[k] - M0); S0 += eb[k];   // invalid slots contribute 0
        ee[k] = __expf(ve[k] - M1); S1 += ee[k];
    }
    #pragma unroll
    for (int o = 16; o > 0; o >>= 1) {
        S0 += __shfl_xor_sync(0xffffffffu, S0, o);
        S1 += __shfl_xor_sync(0xffffffffu, S1, o);
    }
    const float r0 = rcpa(S0) * 128.0f;           // prescale by 2^7 (exact)
    const float r1 = rcpa(S1) * 128.0f;

    float* gb = g_blank + b * SLAB;
    float* ge = g_emit  + b * SLAB;
    #pragma unroll
    for (int k = 0; k < 7; ++k) {
        const int t = lane + 32 * k;
        if (t < T_) {
            gb[(63 + t) * PADW + u] = eb[k] * r0;                  // blank
            if (hasE) ge[(62 + t) * PADW + (u + 1)] = ee[k] * r1;  // emit, col+1
        }
    }
}

// ---------------------------------------------------------------------------
// Kernel B: linear-domain scaled forward DP + final mean. One block/batch;
// warp 0 runs the anti-diagonal wavefront (lane i owns u0=2i, u1=2i+1):
//   n0 = p0*B(t0-1,u0) + lp*E(t0,u0-1)     lp = left lane's p1 (shfl)
//   n1 = p1*B(t1-1,u1) + p0*E(t1,u1-1)
// Warp-uniform power-of-2 renorm every 32 steps (prescaled coefficients);
// frames never diverge -> no per-step frame conversion. Zero margins keep
// the body guard-free. Last finishing block computes the mean (deterministic)
// and resets g_done for graph replay.
// ---------------------------------------------------------------------------
__global__ __launch_bounds__(256) void k_dp(const int* __restrict__ ilen,
                                            const int* __restrict__ tlen,
                                            float*     __restrict__ out) {
    const int b = blockIdx.x;
    extern __shared__ float smem[];
    float* sb = smem;           // [ROWS][PADW] blank slab
    float* se = smem + SLAB;    // [ROWS][PADW] emit slab

    const int ti = ilen[b] - 1;            // [99, 199]
    const int ui = tlen[b] - 1;            // [24, 49]
    const int dmax = ti + ui;

    {   // zero ghost rows; stage only rows 62 .. 62+dmax of both slabs
        float4* s4 = (float4*)smem;
        const float4 z4 = make_float4(0.f, 0.f, 0.f, 0.f);
        const int Q = SLAB / 4;
        for (int i = threadIdx.x; i < 62 * 16; i += 256) {
            s4[i] = z4; s4[i + Q] = z4;
        }
        for (int i = threadIdx.x; i < 48 * 16; i += 256) {
            s4[263 * 16 + i] = z4; s4[263 * 16 + Q + i] = z4;
        }
        const int nrows = min(dmax + 1, 201);
        const float4* gb = (const float4*)(g_blank + b * SLAB);
        const float4* ge = (const float4*)(g_emit  + b * SLAB);
        #pragma unroll 4
        for (int i = threadIdx.x; i < nrows * 16; i += 256) {
            s4[62 * 16 + i]     = gb[62 * 16 + i];
            s4[62 * 16 + Q + i] = ge[62 * 16 + i];
        }
    }
    __syncthreads();
    if (threadIdx.x >= 32) return;         // warp 0 only from here

    const int lane = threadIdx.x;
    int idx = (63 - 2 * lane) * PADW + 2 * lane;   // row of cell (t0,u0) at d=1

    float p0 = (lane == 0) ? 1.0f : 0.0f;  // alpha'[0][0] = 1
    float p1 = 0.0f;
    int   L  = 0;                          // warp-uniform frame exponent

    #define DP_STEP(o)                                                        \
    {                                                                         \
        const float lp  = __shfl_up_sync(0xffffffffu, p1, 1);                 \
        const float cbA = sb[o];                                              \
        const float ceA = se[o];                                              \
        const float cbB = sb[(o) - PADW + 1];                                 \
        const float ceB = se[(o) - PADW + 1];                                 \
        const float n0  = fmaf(p0, cbA, lp * ceA);                            \
        const float n1  = fmaf(p1, cbB, p0 * ceB);                            \
        p0 = n0; p1 = n1;                                                     \
    }

    const int ngroups = dmax >> 5;         // renorm every 32 steps
    for (int g = 0; g < ngroups; ++g) {
        for (int q = 0; q < 4; ++q) {      // 4 x 8-step unrolled (regs stay low)
            #pragma unroll
            for (int k = 0; k < 8; ++k) DP_STEP(idx + k * PADW)
            idx += 8 * PADW;
        }

        // warp-uniform renorm from a reference active lane on diagonal dcur
        const int dcur = 32 * (g + 1);
        int lo = dcur - (T_ - 1);
        lo = (lo > 0) ? ((lo + 1) >> 1) : 0;
        const int hi  = min(ui >> 1, dcur >> 1);
        const int ref = (lo + hi) >> 1;

        float pr = __shfl_sync(0xffffffffu, p0, ref);
        pr = (pr > 0.0f) ? pr : 1.0f;      // degenerate boundary: skip renorm
        const int e = (int)(__float_as_uint(pr) >> 23) - 127;
        L += e;
        const float fs = __uint_as_float((unsigned)(127 - e) << 23);  // 2^-e
        p0 *= fs; p1 *= fs;
    }

    const int tail = dmax & 31;
    for (int k = 0; k < tail; ++k) DP_STEP(idx + k * PADW)

    #undef DP_STEP

    // answer: alpha[ti][ui]*blank = pf*bf * 2^(L - 7*(dmax+1))
    if (lane == (ui >> 1)) {
        const float pf = (ui & 1) ? p1 : p0;
        const float bf = sb[(63 + ti) * PADW + ui];
        g_res[b] = -(lg2a(pf * bf) + (float)(L - 7 * (dmax + 1))) * LN2;
        __threadfence();
        const int old = atomicAdd(&g_done, 1);
        if (old == B_ - 1) {               // last finisher: deterministic mean
            __threadfence();
            float s = 0.0f;
            #pragma unroll
            for (int i = 0; i < B_; ++i) s += g_res[i];
            out[0] = s * (1.0f / B_);
            g_done = 0;                    // reset for next graph replay
            __threadfence();
        }
    }
}

// ---------------------------------------------------------------------------
extern "C" void kernel_launch(void* const* d_in, const int* in_sizes, int n_in,
                              void* d_out, int out_size) {
    const float* h       = (const float*)d_in[0];
    const int*   targets = (const int*)  d_in[1];
    const int*   il      = (const int*)  d_in[2];
    const int*   tl      = (const int*)  d_in[3];
    float*       out     = (float*)d_out;

    const int smem_bytes = 2 * SLAB * (int)sizeof(float);  // 159232
    cudaFuncSetAttribute(k_dp, cudaFuncAttributeMaxDynamicSharedMemorySize,
                         smem_bytes);

    k_lse<<<B_ * U_ / 4, 128>>>(h, targets, tl);
    k_dp <<<B_, 256, smem_bytes>>>(il, tl, out);
}